// round 5
// baseline (speedup 1.0000x reference)
#include <cuda_runtime.h>
#include <cstdint>

// Problem constants (fixed by the dataset)
#define B_  64
#define NH  1024
#define NV  2048

#define THREADS   128
#define VT        (THREADS * 4)   // 512 v-columns per block (float4 per thread)
#define H_SPLIT   4
#define HS        (NH / H_SPLIT)  // 256 h per block
#define RBATCH    8               // rows staged per load/store burst

// out layout: [ b2 : B*NV floats ][ wt2 : B*NH*NV floats ]
#define B2_ELEMS  (B_ * NV)

// ---------------------------------------------------------------------------
// Kernel 1: seed b2 with b1 (b2 then receives atomic partial sums)
// ---------------------------------------------------------------------------
__global__ void init_b2_kernel(const float* __restrict__ b1,
                               float* __restrict__ out_b2) {
    int i = blockIdx.x * blockDim.x + threadIdx.x;   // float4 index
    const float4* src = reinterpret_cast<const float4*>(b1);
    float4*       dst = reinterpret_cast<float4*>(out_b2);
    if (i < B2_ELEMS / 4) dst[i] = src[i];
}

// ---------------------------------------------------------------------------
// Kernel 2: fused  wt2 = scale * wt1  and  b2 += sum_h coeff[h] * wt1[:,h,:]
//   grid: (NV/VT, H_SPLIT, B) = (4, 4, 64) = 1024 CTAs -> single wave
//   Loads and stores are batched RBATCH rows at a time so the HBM controller
//   sees long same-direction bursts (fewer read/write turnarounds).
// ---------------------------------------------------------------------------
__global__ __launch_bounds__(THREADS, 4)
void fused_convert_kernel(const float* __restrict__ wt1,
                          const float* __restrict__ muh1,
                          const float* __restrict__ muh2,
                          const float* __restrict__ varh1,
                          const float* __restrict__ varh2,
                          float* __restrict__ out_b2,
                          float* __restrict__ out_wt2) {
    __shared__ float s_scale[HS];
    __shared__ float s_coeff[HS];

    const int b  = blockIdx.z;
    const int h0 = blockIdx.y * HS;
    const int v0 = blockIdx.x * VT + threadIdx.x * 4;

    // Precompute per-h scale and coeff for this h-range
    for (int i = threadIdx.x; i < HS; i += THREADS) {
        const int idx = b * NH + h0 + i;
        const float sc = sqrtf(varh1[idx]) * rsqrtf(varh2[idx]);
        s_scale[i] = sc;
        s_coeff[i] = fmaf(-sc, muh2[idx], muh1[idx]);
    }
    __syncthreads();

    // float4 pointers; h-stride in float4 units is NV/4
    const size_t base = ((size_t)(b * NH + h0) * NV + v0) >> 2;
    const float4* __restrict__ src = reinterpret_cast<const float4*>(wt1) + base;
    float4*       __restrict__ dst = reinterpret_cast<float4*>(out_wt2) + base;
    const int hstride = NV / 4;

    float4 acc = make_float4(0.f, 0.f, 0.f, 0.f);

    for (int i = 0; i < HS; i += RBATCH) {
        float4 w[RBATCH];

        // Burst of RBATCH independent 16B loads (read phase)
        #pragma unroll
        for (int j = 0; j < RBATCH; ++j)
            w[j] = __ldg(src + (size_t)(i + j) * hstride);

        // Compute + burst of RBATCH stores (write phase)
        #pragma unroll
        for (int j = 0; j < RBATCH; ++j) {
            const float sc = s_scale[i + j];
            const float cf = s_coeff[i + j];

            acc.x = fmaf(w[j].x, cf, acc.x);
            acc.y = fmaf(w[j].y, cf, acc.y);
            acc.z = fmaf(w[j].z, cf, acc.z);
            acc.w = fmaf(w[j].w, cf, acc.w);

            float4 o;
            o.x = w[j].x * sc; o.y = w[j].y * sc;
            o.z = w[j].z * sc; o.w = w[j].w * sc;
            dst[(size_t)(i + j) * hstride] = o;
        }
    }

    // Partial b2 contribution from this h-split (REDG, distinct addresses)
    float* b2p = out_b2 + (size_t)b * NV + v0;
    atomicAdd(b2p + 0, acc.x);
    atomicAdd(b2p + 1, acc.y);
    atomicAdd(b2p + 2, acc.z);
    atomicAdd(b2p + 3, acc.w);
}

// ---------------------------------------------------------------------------
// Launch
// Inputs (metadata order): b1, wt1, muh1, muh2, varh_diag1, varh_diag2
// Output: [b2 | wt2]
// ---------------------------------------------------------------------------
extern "C" void kernel_launch(void* const* d_in, const int* in_sizes, int n_in,
                              void* d_out, int out_size) {
    const float* b1    = (const float*)d_in[0];
    const float* wt1   = (const float*)d_in[1];
    const float* muh1  = (const float*)d_in[2];
    const float* muh2  = (const float*)d_in[3];
    const float* varh1 = (const float*)d_in[4];
    const float* varh2 = (const float*)d_in[5];

    float* out_b2  = (float*)d_out;
    float* out_wt2 = out_b2 + B2_ELEMS;

    init_b2_kernel<<<(B2_ELEMS / 4 + 255) / 256, 256>>>(b1, out_b2);

    dim3 grid(NV / VT, H_SPLIT, B_);
    fused_convert_kernel<<<grid, THREADS>>>(wt1, muh1, muh2, varh1, varh2,
                                            out_b2, out_wt2);
}

// round 7
// speedup vs baseline: 1.0004x; 1.0004x over previous
#include <cuda_runtime.h>
#include <cstdint>

// Problem constants (fixed by the dataset)
#define B_  64
#define NH  1024
#define NV  2048

#define THREADS   128
#define VT        (THREADS * 4)   // 512 v-columns per block (float4 per thread)
#define H_SPLIT   4
#define HS        (NH / H_SPLIT)  // 256 h per block
#define RBATCH    8               // rows staged per load/store burst

// out layout: [ b2 : B*NV floats ][ wt2 : B*NH*NV floats ]
#define B2_ELEMS  (B_ * NV)

// ---------------------------------------------------------------------------
// Fused kernel:  wt2 = scale * wt1  and  b2 += sum_h coeff[h] * wt1[:,h,:]
//   grid: (NV/VT, H_SPLIT, B) = (4, 4, 64) = 1024 CTAs -> single wave
//   Loads and stores are batched RBATCH rows at a time so the HBM controller
//   sees long same-direction bursts (fewer read/write turnarounds).
// ---------------------------------------------------------------------------
__global__ __launch_bounds__(THREADS, 4)
void fused_convert_kernel(const float* __restrict__ wt1,
                          const float* __restrict__ muh1,
                          const float* __restrict__ muh2,
                          const float* __restrict__ varh1,
                          const float* __restrict__ varh2,
                          float* __restrict__ out_b2,
                          float* __restrict__ out_wt2) {
    __shared__ float s_scale[HS];
    __shared__ float s_coeff[HS];

    const int b  = blockIdx.z;
    const int h0 = blockIdx.y * HS;
    const int v0 = blockIdx.x * VT + threadIdx.x * 4;

    // Precompute per-h scale and coeff for this h-range
    for (int i = threadIdx.x; i < HS; i += THREADS) {
        const int idx = b * NH + h0 + i;
        const float sc = sqrtf(varh1[idx]) * rsqrtf(varh2[idx]);
        s_scale[i] = sc;
        s_coeff[i] = fmaf(-sc, muh2[idx], muh1[idx]);
    }
    __syncthreads();

    // float4 pointers; h-stride in float4 units is NV/4
    const size_t base = ((size_t)(b * NH + h0) * NV + v0) >> 2;
    const float4* __restrict__ src = reinterpret_cast<const float4*>(wt1) + base;
    float4*       __restrict__ dst = reinterpret_cast<float4*>(out_wt2) + base;
    const int hstride = NV / 4;

    float4 acc = make_float4(0.f, 0.f, 0.f, 0.f);

    for (int i = 0; i < HS; i += RBATCH) {
        float4 w[RBATCH];

        // Burst of RBATCH independent 16B loads (read phase)
        #pragma unroll
        for (int j = 0; j < RBATCH; ++j)
            w[j] = __ldg(src + (size_t)(i + j) * hstride);

        // Compute + burst of RBATCH stores (write phase)
        #pragma unroll
        for (int j = 0; j < RBATCH; ++j) {
            const float sc = s_scale[i + j];
            const float cf = s_coeff[i + j];

            acc.x = fmaf(w[j].x, cf, acc.x);
            acc.y = fmaf(w[j].y, cf, acc.y);
            acc.z = fmaf(w[j].z, cf, acc.z);
            acc.w = fmaf(w[j].w, cf, acc.w);

            float4 o;
            o.x = w[j].x * sc; o.y = w[j].y * sc;
            o.z = w[j].z * sc; o.w = w[j].w * sc;
            dst[(size_t)(i + j) * hstride] = o;
        }
    }

    // Partial b2 contribution from this h-split (REDG, distinct addresses)
    float* b2p = out_b2 + (size_t)b * NV + v0;
    atomicAdd(b2p + 0, acc.x);
    atomicAdd(b2p + 1, acc.y);
    atomicAdd(b2p + 2, acc.z);
    atomicAdd(b2p + 3, acc.w);
}

// ---------------------------------------------------------------------------
// Launch
// Inputs (metadata order): b1, wt1, muh1, muh2, varh_diag1, varh_diag2
// Output: [b2 | wt2]
// ---------------------------------------------------------------------------
extern "C" void kernel_launch(void* const* d_in, const int* in_sizes, int n_in,
                              void* d_out, int out_size) {
    const float* b1    = (const float*)d_in[0];
    const float* wt1   = (const float*)d_in[1];
    const float* muh1  = (const float*)d_in[2];
    const float* muh2  = (const float*)d_in[3];
    const float* varh1 = (const float*)d_in[4];
    const float* varh2 = (const float*)d_in[5];

    float* out_b2  = (float*)d_out;
    float* out_wt2 = out_b2 + B2_ELEMS;

    // Seed b2 with b1 via copy engine (graph-capturable, cheaper than a
    // kernel node); fused kernel then accumulates partial sums atomically.
    cudaMemcpyAsync(out_b2, b1, (size_t)B2_ELEMS * sizeof(float),
                    cudaMemcpyDeviceToDevice);

    dim3 grid(NV / VT, H_SPLIT, B_);
    fused_convert_kernel<<<grid, THREADS>>>(wt1, muh1, muh2, varh1, varh2,
                                            out_b2, out_wt2);
}

// round 8
// speedup vs baseline: 1.0035x; 1.0032x over previous
#include <cuda_runtime.h>
#include <cstdint>

// Problem constants (fixed by the dataset)
#define B_  64
#define NH  1024
#define NV  2048

#define THREADS   128
#define VT        (THREADS * 4)   // 512 v-columns per block (float4 per thread)
#define H_SPLIT   4
#define HS        (NH / H_SPLIT)  // 256 h per block
#define RBATCH    8               // rows staged per load/store burst
#define XBLOCKS   (NV / VT)       // 4

// out layout: [ b2 : B*NV floats ][ wt2 : B*NH*NV floats ]
#define B2_ELEMS  (B_ * NV)

// Scratch for b2 partial sums (one slab per h-split) and completion counters.
// __device__ globals: allowed (no dynamic allocation).
__device__ float        g_partial[H_SPLIT * B_ * NV];       // 2 MB
__device__ unsigned int g_count[B_ * XBLOCKS];              // zero-init

// ---------------------------------------------------------------------------
// Single fused kernel:
//   wt2 = scale * wt1
//   b2  = b1 + sum_h coeff[h] * wt1[:,h,:]   (split-h partials + last-block reduce)
// grid: (XBLOCKS, H_SPLIT, B) = (4,4,64) = 1024 CTAs -> single wave @ 7 CTA/SM
// ---------------------------------------------------------------------------
__global__ __launch_bounds__(THREADS, 7)
void fused_convert_kernel(const float* __restrict__ b1,
                          const float* __restrict__ wt1,
                          const float* __restrict__ muh1,
                          const float* __restrict__ muh2,
                          const float* __restrict__ varh1,
                          const float* __restrict__ varh2,
                          float* __restrict__ out_b2,
                          float* __restrict__ out_wt2) {
    __shared__ float s_scale[HS];
    __shared__ float s_coeff[HS];
    __shared__ unsigned int s_ticket;

    const int b  = blockIdx.z;
    const int h0 = blockIdx.y * HS;
    const int v0 = blockIdx.x * VT + threadIdx.x * 4;

    // Precompute per-h scale and coeff for this h-range
    for (int i = threadIdx.x; i < HS; i += THREADS) {
        const int idx = b * NH + h0 + i;
        const float sc = sqrtf(varh1[idx]) * rsqrtf(varh2[idx]);
        s_scale[i] = sc;
        s_coeff[i] = fmaf(-sc, muh2[idx], muh1[idx]);
    }
    __syncthreads();

    // float4 pointers; h-stride in float4 units is NV/4
    const size_t base = ((size_t)(b * NH + h0) * NV + v0) >> 2;
    const float4* __restrict__ src = reinterpret_cast<const float4*>(wt1) + base;
    float4*       __restrict__ dst = reinterpret_cast<float4*>(out_wt2) + base;
    const int hstride = NV / 4;

    float4 acc = make_float4(0.f, 0.f, 0.f, 0.f);

    for (int i = 0; i < HS; i += RBATCH) {
        float4 w[RBATCH];

        // Burst of RBATCH independent 16B loads (read phase)
        #pragma unroll
        for (int j = 0; j < RBATCH; ++j)
            w[j] = __ldg(src + (size_t)(i + j) * hstride);

        // Compute + burst of RBATCH stores (write phase)
        #pragma unroll
        for (int j = 0; j < RBATCH; ++j) {
            const float sc = s_scale[i + j];
            const float cf = s_coeff[i + j];

            acc.x = fmaf(w[j].x, cf, acc.x);
            acc.y = fmaf(w[j].y, cf, acc.y);
            acc.z = fmaf(w[j].z, cf, acc.z);
            acc.w = fmaf(w[j].w, cf, acc.w);

            float4 o;
            o.x = w[j].x * sc; o.y = w[j].y * sc;
            o.z = w[j].z * sc; o.w = w[j].w * sc;
            dst[(size_t)(i + j) * hstride] = o;
        }
    }

    // ---- b2 partial: plain coalesced store to scratch, then ticket ----
    {
        float4* part = reinterpret_cast<float4*>(
            g_partial + ((size_t)blockIdx.y * B_ + b) * NV + v0);
        part[0] = acc;
    }
    __threadfence();        // make partial visible before the ticket
    __syncthreads();        // all threads' partials stored

    if (threadIdx.x == 0)
        s_ticket = atomicAdd(&g_count[b * XBLOCKS + blockIdx.x], 1u);
    __syncthreads();

    if (s_ticket == H_SPLIT - 1) {
        // Last block of this (b, v-window) group: reduce partials + b1 -> b2
        const size_t voff = (size_t)b * NV + v0;
        float4 sum = *reinterpret_cast<const float4*>(b1 + voff);
        #pragma unroll
        for (int s = 0; s < H_SPLIT; ++s) {
            const float4 p = *reinterpret_cast<const float4*>(
                g_partial + ((size_t)s * B_ + b) * NV + v0);
            sum.x += p.x; sum.y += p.y; sum.z += p.z; sum.w += p.w;
        }
        *reinterpret_cast<float4*>(out_b2 + voff) = sum;

        // Reset counter for the next graph replay (deterministic)
        if (threadIdx.x == 0)
            g_count[b * XBLOCKS + blockIdx.x] = 0u;
    }
}

// ---------------------------------------------------------------------------
// Launch — single kernel node
// Inputs (metadata order): b1, wt1, muh1, muh2, varh_diag1, varh_diag2
// Output: [b2 | wt2]
// ---------------------------------------------------------------------------
extern "C" void kernel_launch(void* const* d_in, const int* in_sizes, int n_in,
                              void* d_out, int out_size) {
    const float* b1    = (const float*)d_in[0];
    const float* wt1   = (const float*)d_in[1];
    const float* muh1  = (const float*)d_in[2];
    const float* muh2  = (const float*)d_in[3];
    const float* varh1 = (const float*)d_in[4];
    const float* varh2 = (const float*)d_in[5];

    float* out_b2  = (float*)d_out;
    float* out_wt2 = out_b2 + B2_ELEMS;

    dim3 grid(XBLOCKS, H_SPLIT, B_);
    fused_convert_kernel<<<grid, THREADS>>>(b1, wt1, muh1, muh2, varh1, varh2,
                                            out_b2, out_wt2);
}